// round 2
// baseline (speedup 1.0000x reference)
#include <cuda_runtime.h>
#include <math.h>

// Problem constants
#define M    129         // mesh points per dim (odd)
#define MH   65          // half-spectrum rows: k1 = 0..64
#define NB   4           // batch
#define NP   512         // points per batch
#define NPTS (NB*NP)     // 2048
#define WSUP 7           // gaussian support half-width (tail at d=8 ~ 1e-23)
#define NW   15          // taps = 2*WSUP+1
#define RJ   5           // k1 rows per k_S block (13*5 = 65)
#define PCH  64          // points per k_S chunk (512/64 = 8 chunks)
#define NCH  8

// Scratch (__device__ globals: no allocations allowed)
__device__ float2 g_Gx[NPTS*MH];          // per-point x-spectrum, k1 = 0..64
__device__ float2 g_Gy[NPTS*M];           // per-point y-spectrum, k2 = -64..64 (j2 = k2+64)
__device__ float2 g_Spart[NCH*NB*MH*M];   // partial per-batch spectrum sums (8 chunks)
__device__ float2 g_S [NB*MH*M];          // per-batch sum of F_q over half spectrum
__device__ float2 g_D [MH*M];             // {D_ch0, D_ch1} multipliers (constants + fold baked in)

// ---------------------------------------------------------------- per-point 1D spectra
__device__ __forceinline__ float gper(float x) {
    const float INV4 = (float)(129.0 * 129.0 / 48.0);   // 1/(4*tau), tau = 12/M^2
    const float L    = (float)(2.0 * 3.14159265358979323846);
    return expf(-x * x * INV4)
         + expf(-(x - L) * (x - L) * INV4)
         + expf(-(x + L) * (x + L) * INV4);
}

__global__ void k_spectra(const float* __restrict__ X) {
    int p   = blockIdx.x;       // global point index 0..2047
    int tid = threadIdx.x;      // 128 threads
    __shared__ float2 cis[M];   // exp(-2*pi*i*t/M)
    __shared__ float  wgt[2][NW];

    // cis table (accurate sincosf; error ~4e-7, irrelevant at 1e-3 tol)
    for (int t = tid; t < M; t += 128) {
        float ang = (float)t * (float)(-2.0 * 3.14159265358979323846 / 129.0);
        float s, c;
        sincosf(ang, &s, &c);
        cis[t] = make_float2(c, s);
    }

    float x0 = X[2 * p];
    float y0 = X[2 * p + 1];
    const float H    = (float)(2.0 * 3.14159265358979323846 / 129.0);
    const float INVH = (float)(129.0 / (2.0 * 3.14159265358979323846));
    int i0x = (int)floorf(x0 * INVH + 0.5f);
    int i0y = (int)floorf(y0 * INVH + 0.5f);

    if (tid < 2 * NW) {
        int dim = tid / NW;
        int d   = tid - dim * NW;
        float xv = dim ? y0 : x0;
        int   i0 = dim ? i0y : i0x;
        int i  = i0 - WSUP + d;
        int iw = i % M; if (iw < 0) iw += M;        // wrapped grid index (matches reference arg)
        wgt[dim][d] = gper(xv - (float)iw * H);
    }
    __syncthreads();

    // 65 x-outputs (k=0..64) + 129 y-outputs (k=-64..64)
    for (int o = tid; o < MH + M; o += 128) {
        bool isX = (o < MH);
        int k  = isX ? o : (o - MH - 64);
        int i0 = isX ? i0x : i0y;
        const float* w = wgt[isX ? 0 : 1];
        int iw0 = i0 - WSUP;
        int t = (k * iw0) % M; if (t < 0) t += M;   // phase index k*i mod M (exact integers)
        int ks = k; if (ks < 0) ks += M;
        float re = 0.0f, im = 0.0f;
        #pragma unroll
        for (int d = 0; d < NW; d++) {
            float2 c = cis[t];
            re = fmaf(w[d], c.x, re);
            im = fmaf(w[d], c.y, im);
            t += ks; if (t >= M) t -= M;
        }
        if (isX) g_Gx[p * MH + o]        = make_float2(re, im);
        else     g_Gy[p * M + (o - MH)]  = make_float2(re, im);
    }
}

// ---------------------------------------------------------------- per-batch partial S
// S_b(k1,k2) = sum_q Gx_q(k1) * Gy_q(k2); split the point sum into NCH chunks for parallelism.
__global__ void k_S() {
    int j1b = blockIdx.x * RJ;        // 13 row tiles
    int b   = blockIdx.y;             // 4 batches
    int pz  = blockIdx.z;             // 8 point chunks
    int tid = threadIdx.x;            // 160 threads (129 active in compute)
    __shared__ float2 sgx[PCH * RJ];

    int p0 = b * NP + pz * PCH;
    if (tid < PCH) {
        #pragma unroll
        for (int r = 0; r < RJ; r++)
            sgx[tid * RJ + r] = g_Gx[(p0 + tid) * MH + j1b + r];
    }
    __syncthreads();

    if (tid < M) {
        float2 acc[RJ];
        #pragma unroll
        for (int r = 0; r < RJ; r++) acc[r] = make_float2(0.0f, 0.0f);

        for (int pl = 0; pl < PCH; pl++) {
            float2 gy = __ldg(&g_Gy[(p0 + pl) * M + tid]);
            #pragma unroll
            for (int r = 0; r < RJ; r++) {
                float2 gx = sgx[pl * RJ + r];
                acc[r].x = fmaf(gx.x, gy.x, fmaf(-gx.y, gy.y, acc[r].x));
                acc[r].y = fmaf(gx.x, gy.y, fmaf( gx.y, gy.x, acc[r].y));
            }
        }
        #pragma unroll
        for (int r = 0; r < RJ; r++)
            g_Spart[pz * (NB * MH * M) + ((b * MH + j1b + r) * M + tid)] = acc[r];
    }
}

// ---------------------------------------------------------------- reduce partials + build D
// D_c(k1,k2) = wfold * (pi/288) * exp(2*tau*|k|^2) * amp_c / (|k|^2 + (mu_c*shift_c)^2)
// (pi/288 = scale/M^2 * (pi/tau)^2 * 4*pi with tau = 12/M^2, L = 2*pi; mu0 = mu1 = 1)
__global__ void k_Sreduce_D(const float* __restrict__ s0, const float* __restrict__ s1,
                            const float* __restrict__ a0, const float* __restrict__ a1) {
    int idx = blockIdx.x * blockDim.x + threadIdx.x;
    if (idx < NB * MH * M) {
        float2 acc = make_float2(0.0f, 0.0f);
        #pragma unroll
        for (int c = 0; c < NCH; c++) {           // fixed order: deterministic
            float2 v = g_Spart[c * (NB * MH * M) + idx];
            acc.x += v.x; acc.y += v.y;
        }
        g_S[idx] = acc;
    }
    if (idx < MH * M) {
        int j1 = idx / M;
        int j2 = idx - j1 * M;
        float k1 = (float)j1;
        float k2 = (float)(j2 - 64);
        float ks = k1 * k1 + k2 * k2;
        const float TAU  = (float)(12.0 / (129.0 * 129.0));
        const float PREF = (float)(3.14159265358979323846 / 288.0);
        float wf   = (j1 == 0) ? 1.0f : 2.0f;     // conjugate-symmetry fold weight
        float base = wf * PREF * expf(2.0f * TAU * ks);
        float m0 = s0[0];                          // mu0 * shift0, mu0 = 1
        float m1 = s1[0];                          // mu1 * shift1, mu1 = 1
        g_D[idx] = make_float2(base * a0[0] / (ks + m0 * m0),
                               base * a1[0] / (ks + m1 * m1));
    }
}

// ---------------------------------------------------------------- energies
// e[b,p,c] = sum_k D_c(k) * ( Re(S(k) * conj(F_p(k))) - |F_p(k)|^2 ),  F_p = Gx_p (x) Gy_p
#define PPB 8   // points per block
__global__ void k_energy(float* __restrict__ out) {
    int b     = blockIdx.x >> 6;
    int grp   = blockIdx.x & 63;
    int pbase = b * NP + grp * PPB;   // global point index of first point in group
    int tid   = threadIdx.x;          // 256 threads = 8 warps

    __shared__ float2 sGx[PPB * MH];
    __shared__ float2 sGy[PPB * M];
    __shared__ float  wred[8][2 * PPB];

    for (int i = tid; i < PPB * MH; i += 256) {
        int pp = i / MH; int j = i - pp * MH;
        sGx[i] = g_Gx[(pbase + pp) * MH + j];
    }
    for (int i = tid; i < PPB * M; i += 256) {
        int pp = i / M; int j = i - pp * M;
        sGy[i] = g_Gy[(pbase + pp) * M + j];
    }
    __syncthreads();

    float acc0[PPB], acc1[PPB];
    #pragma unroll
    for (int pp = 0; pp < PPB; pp++) { acc0[pp] = 0.0f; acc1[pp] = 0.0f; }

    const float2* Sb = g_S + b * MH * M;
    for (int q = tid; q < MH * M; q += 256) {
        int j1 = q / M;
        int j2 = q - j1 * M;
        float2 S  = __ldg(&Sb[q]);
        float2 Dp = __ldg(&g_D[q]);
        #pragma unroll
        for (int pp = 0; pp < PPB; pp++) {
            float2 gx = sGx[pp * MH + j1];
            float2 gy = sGy[pp * M + j2];
            float Fre = gx.x * gy.x - gx.y * gy.y;
            float Fim = gx.x * gy.y + gx.y * gy.x;
            float u = fmaf(S.x, Fre, S.y * Fim) - fmaf(Fre, Fre, Fim * Fim);
            acc0[pp] = fmaf(Dp.x, u, acc0[pp]);
            acc1[pp] = fmaf(Dp.y, u, acc1[pp]);
        }
    }

    int lane = tid & 31, wid = tid >> 5;
    #pragma unroll
    for (int pp = 0; pp < PPB; pp++) {
        float v0 = acc0[pp], v1 = acc1[pp];
        #pragma unroll
        for (int s = 16; s > 0; s >>= 1) {
            v0 += __shfl_down_sync(0xffffffffu, v0, s);
            v1 += __shfl_down_sync(0xffffffffu, v1, s);
        }
        if (lane == 0) { wred[wid][2 * pp] = v0; wred[wid][2 * pp + 1] = v1; }
    }
    __syncthreads();
    if (tid < 2 * PPB) {                       // deterministic tree finish (no float atomics)
        float s = 0.0f;
        #pragma unroll
        for (int w = 0; w < 8; w++) s += wred[w][tid];
        out[pbase * 2 + tid] = s;              // tid = pp*2 + c
    }
}

// ---------------------------------------------------------------- launch
extern "C" void kernel_launch(void* const* d_in, const int* in_sizes, int n_in,
                              void* d_out, int out_size) {
    const float* x  = (const float*)d_in[0];  // [4,512,2]
    const float* s0 = (const float*)d_in[1];  // shift0 [1]
    const float* s1 = (const float*)d_in[2];  // shift1 [1]
    const float* a0 = (const float*)d_in[3];  // amp0   [1]
    const float* a1 = (const float*)d_in[4];  // amp1   [1]
    float* out = (float*)d_out;               // [4,512,2]

    k_spectra<<<NPTS, 128>>>(x);
    k_S<<<dim3(13, NB, NCH), 160>>>();
    k_Sreduce_D<<<(NB * MH * M + 255) / 256, 256>>>(s0, s1, a0, a1);
    k_energy<<<NB * 64, 256>>>(out);
}

// round 9
// speedup vs baseline: 1.1514x; 1.1514x over previous
#include <cuda_runtime.h>
#include <math.h>

// Problem constants
#define M    129         // mesh points per dim (odd)
#define MH   65          // half-spectrum rows: k1 = 0..64
#define NB   4           // batch
#define NP   512         // points per batch
#define NPTS (NB*NP)     // 2048
#define WSUP 7           // gaussian support half-width (tail at d=8 ~ 1e-23)
#define NW   15          // taps = 2*WSUP+1
#define RJ   5           // k1 rows per k_S block (13*5 = 65)
#define PCH  64          // points per k_S chunk (512/64 = 8 chunks)
#define NCH  8

// Scratch (__device__ globals: no allocations allowed)
__device__ float2 g_Gx[NPTS*MH];          // per-point x-spectrum, k1 = 0..64
__device__ float2 g_Gy[NPTS*M];           // per-point y-spectrum, k2 = -64..64 (j2 = k2+64)
__device__ float2 g_Spart[NCH*NB*MH*M];   // partial per-batch spectrum sums (8 chunks)
__device__ float4 g_SD[NB*MH*M];          // packed (S.re, S.im, D0, D1) per batch & k-point

// ---------------------------------------------------------------- per-point 1D spectra
__device__ __forceinline__ float gper(float x) {
    const float INV4 = (float)(129.0 * 129.0 / 48.0);   // 1/(4*tau), tau = 12/M^2
    const float L    = (float)(2.0 * 3.14159265358979323846);
    return expf(-x * x * INV4)
         + expf(-(x - L) * (x - L) * INV4)
         + expf(-(x + L) * (x + L) * INV4);
}

__global__ void k_spectra(const float* __restrict__ X) {
    int p   = blockIdx.x;       // global point index 0..2047
    int tid = threadIdx.x;      // 128 threads
    __shared__ float2 cis[M];   // exp(-2*pi*i*t/M)
    __shared__ float  wgt[2][NW];

    for (int t = tid; t < M; t += 128) {
        float ang = (float)t * (float)(-2.0 * 3.14159265358979323846 / 129.0);
        float s, c;
        sincosf(ang, &s, &c);
        cis[t] = make_float2(c, s);
    }

    float x0 = X[2 * p];
    float y0 = X[2 * p + 1];
    const float H    = (float)(2.0 * 3.14159265358979323846 / 129.0);
    const float INVH = (float)(129.0 / (2.0 * 3.14159265358979323846));
    int i0x = (int)floorf(x0 * INVH + 0.5f);
    int i0y = (int)floorf(y0 * INVH + 0.5f);

    if (tid < 2 * NW) {
        int dim = tid / NW;
        int d   = tid - dim * NW;
        float xv = dim ? y0 : x0;
        int   i0 = dim ? i0y : i0x;
        int i  = i0 - WSUP + d;
        int iw = i % M; if (iw < 0) iw += M;        // wrapped grid index (matches reference arg)
        wgt[dim][d] = gper(xv - (float)iw * H);
    }
    __syncthreads();

    // 65 x-outputs (k=0..64) + 129 y-outputs (k=-64..64)
    for (int o = tid; o < MH + M; o += 128) {
        bool isX = (o < MH);
        int k  = isX ? o : (o - MH - 64);
        int i0 = isX ? i0x : i0y;
        const float* w = wgt[isX ? 0 : 1];
        int iw0 = i0 - WSUP;
        int t = (k * iw0) % M; if (t < 0) t += M;   // phase index k*i mod M (exact integers)
        int ks = k; if (ks < 0) ks += M;
        float re = 0.0f, im = 0.0f;
        #pragma unroll
        for (int d = 0; d < NW; d++) {
            float2 c = cis[t];
            re = fmaf(w[d], c.x, re);
            im = fmaf(w[d], c.y, im);
            t += ks; if (t >= M) t -= M;
        }
        if (isX) g_Gx[p * MH + o]        = make_float2(re, im);
        else     g_Gy[p * M + (o - MH)]  = make_float2(re, im);
    }
}

// ---------------------------------------------------------------- per-batch partial S
// S_b(k1,k2) = sum_q Gx_q(k1) * Gy_q(k2); point sum split into NCH chunks for parallelism.
__global__ void k_S() {
    int j1b = blockIdx.x * RJ;        // 13 row tiles
    int b   = blockIdx.y;             // 4 batches
    int pz  = blockIdx.z;             // 8 point chunks
    int tid = threadIdx.x;            // 160 threads (129 active in compute)
    __shared__ float2 sgx[PCH * RJ];

    int p0 = b * NP + pz * PCH;
    if (tid < PCH) {
        #pragma unroll
        for (int r = 0; r < RJ; r++)
            sgx[tid * RJ + r] = g_Gx[(p0 + tid) * MH + j1b + r];
    }
    __syncthreads();

    if (tid < M) {
        float2 acc[RJ];
        #pragma unroll
        for (int r = 0; r < RJ; r++) acc[r] = make_float2(0.0f, 0.0f);

        for (int pl = 0; pl < PCH; pl++) {
            float2 gy = __ldg(&g_Gy[(p0 + pl) * M + tid]);
            #pragma unroll
            for (int r = 0; r < RJ; r++) {
                float2 gx = sgx[pl * RJ + r];
                acc[r].x = fmaf(gx.x, gy.x, fmaf(-gx.y, gy.y, acc[r].x));
                acc[r].y = fmaf(gx.x, gy.y, fmaf( gx.y, gy.x, acc[r].y));
            }
        }
        #pragma unroll
        for (int r = 0; r < RJ; r++)
            g_Spart[pz * (NB * MH * M) + ((b * MH + j1b + r) * M + tid)] = acc[r];
    }
}

// ---------------------------------------------------------------- reduce partials + pack S with D
// D_c(k) = wfold * (pi/288) * exp(2*tau*|k|^2) * amp_c / (|k|^2 + (mu_c*shift_c)^2)
// (pi/288 = scale/M^2 * (pi/tau)^2 * 4*pi, tau = 12/M^2, L = 2*pi; mu0 = mu1 = 1)
__global__ void k_Sreduce_D(const float* __restrict__ s0, const float* __restrict__ s1,
                            const float* __restrict__ a0, const float* __restrict__ a1) {
    int idx = blockIdx.x * blockDim.x + threadIdx.x;   // over NB*MH*M
    if (idx >= NB * MH * M) return;

    float2 acc = make_float2(0.0f, 0.0f);
    #pragma unroll
    for (int c = 0; c < NCH; c++) {           // fixed order: deterministic
        float2 v = g_Spart[c * (NB * MH * M) + idx];
        acc.x += v.x; acc.y += v.y;
    }

    int kk = idx % (MH * M);                  // k-point index within one batch
    int j1 = kk / M;
    int j2 = kk - j1 * M;
    float k1 = (float)j1;
    float k2 = (float)(j2 - 64);
    float ks = k1 * k1 + k2 * k2;
    const float TAU  = (float)(12.0 / (129.0 * 129.0));
    const float PREF = (float)(3.14159265358979323846 / 288.0);
    float wf   = (j1 == 0) ? 1.0f : 2.0f;     // conjugate-symmetry fold weight
    float base = wf * PREF * expf(2.0f * TAU * ks);
    float m0 = s0[0];                          // mu0 * shift0, mu0 = 1
    float m1 = s1[0];                          // mu1 * shift1, mu1 = 1
    g_SD[idx] = make_float4(acc.x, acc.y,
                            base * a0[0] / (ks + m0 * m0),
                            base * a1[0] / (ks + m1 * m1));
}

// ---------------------------------------------------------------- energies
// e[b,p,c] = sum_k D_c(k) * ( Fre*(Sx-Fre) + Fim*(Sy-Fim) ),  F_p = Gx_p (x) Gy_p
#define PPB 8    // points per block
#define NWP 16   // warps per block (512 threads)
__global__ void __launch_bounds__(512, 2) k_energy(float* __restrict__ out) {
    int b     = blockIdx.x >> 6;
    int grp   = blockIdx.x & 63;
    int pbase = b * NP + grp * PPB;   // global point index of first point in group
    int tid   = threadIdx.x;          // 512 threads = 16 warps
    int lane  = tid & 31, w = tid >> 5;

    __shared__ float2 sGx[PPB * MH];
    __shared__ float2 sGy[PPB * M];
    __shared__ float  wred[NWP][2 * PPB];

    for (int i = tid; i < PPB * MH; i += 512) {
        int pp = i / MH; int j = i - pp * MH;
        sGx[i] = g_Gx[(pbase + pp) * MH + j];
    }
    for (int i = tid; i < PPB * M; i += 512) {
        int pp = i / M; int j = i - pp * M;
        sGy[i] = g_Gy[(pbase + pp) * M + j];
    }
    __syncthreads();

    float acc0[PPB], acc1[PPB];
    #pragma unroll
    for (int pp = 0; pp < PPB; pp++) { acc0[pp] = 0.0f; acc1[pp] = 0.0f; }

    const float4* SDb = g_SD + b * MH * M;
    for (int r = w; r < MH; r += NWP) {           // row-per-warp
        float2 gx[PPB];                            // hoist gx into registers (broadcast LDS)
        #pragma unroll
        for (int pp = 0; pp < PPB; pp++) gx[pp] = sGx[pp * MH + r];
        const float4* SDrow = SDb + r * M;
        for (int j2 = lane; j2 < M; j2 += 32) {    // coalesced LDG.128, conflict-free gy
            float4 SD = __ldg(&SDrow[j2]);         // (S.re, S.im, D0, D1)
            #pragma unroll
            for (int pp = 0; pp < PPB; pp++) {
                float2 gy = sGy[pp * M + j2];
                float Fre = gx[pp].x * gy.x - gx[pp].y * gy.y;
                float Fim = gx[pp].x * gy.y + gx[pp].y * gy.x;
                float u = fmaf(Fre, SD.x - Fre, Fim * (SD.y - Fim));
                acc0[pp] = fmaf(SD.z, u, acc0[pp]);
                acc1[pp] = fmaf(SD.w, u, acc1[pp]);
            }
        }
    }

    #pragma unroll
    for (int pp = 0; pp < PPB; pp++) {
        float v0 = acc0[pp], v1 = acc1[pp];
        #pragma unroll
        for (int s = 16; s > 0; s >>= 1) {
            v0 += __shfl_down_sync(0xffffffffu, v0, s);
            v1 += __shfl_down_sync(0xffffffffu, v1, s);
        }
        if (lane == 0) { wred[w][2 * pp] = v0; wred[w][2 * pp + 1] = v1; }
    }
    __syncthreads();
    if (tid < 2 * PPB) {                       // deterministic tree finish (no float atomics)
        float s = 0.0f;
        #pragma unroll
        for (int ww = 0; ww < NWP; ww++) s += wred[ww][tid];
        out[pbase * 2 + tid] = s;              // tid = pp*2 + c
    }
}

// ---------------------------------------------------------------- launch
extern "C" void kernel_launch(void* const* d_in, const int* in_sizes, int n_in,
                              void* d_out, int out_size) {
    const float* x  = (const float*)d_in[0];  // [4,512,2]
    const float* s0 = (const float*)d_in[1];  // shift0 [1]
    const float* s1 = (const float*)d_in[2];  // shift1 [1]
    const float* a0 = (const float*)d_in[3];  // amp0   [1]
    const float* a1 = (const float*)d_in[4];  // amp1   [1]
    float* out = (float*)d_out;               // [4,512,2]

    k_spectra<<<NPTS, 128>>>(x);
    k_S<<<dim3(13, NB, NCH), 160>>>();
    k_Sreduce_D<<<(NB * MH * M + 255) / 256, 256>>>(s0, s1, a0, a1);
    k_energy<<<NB * 64, 512>>>(out);
}